// round 4
// baseline (speedup 1.0000x reference)
#include <cuda_runtime.h>
#include <math.h>

#define NN 50000
#define EE 800000
#define HID 128
#define GG 128
#define LAT 32
#define NEG 0.2f

// ---------------- scratch (static device memory; zero-initialized) ----------------
__device__ float g_h[NN * HID];
__device__ float g_y[NN * HID];
__device__ float g_as[NN * 4];
__device__ float g_ad[NN * 4];
__device__ int   g_deg[NN];          // invariant: zero before/after each launch
__device__ int   g_rowoff[NN + 1];
__device__ int   g_cur[NN];
__device__ int   g_csr[EE + NN];
__device__ int   g_goff[GG + 1];
__device__ float g_pool[GG * HID];

#define FFMA2(d, a, b, c) \
    asm("fma.rn.f32x2 %0, %1, %2, %3;" : "=l"(d) : "l"(a), "l"(b), "l"(c))

// ---------------- CSR build ----------------
__global__ void hist_kernel(const int* __restrict__ dst) {
    int i = blockIdx.x * blockDim.x + threadIdx.x;
    if (i < EE) atomicAdd(&g_deg[dst[i]], 1);
}

// reads g_deg (+1 self loop), builds rowoff/cur, and RE-ZEROES g_deg so the
// zero-invariant holds across graph replays.
__global__ void scan_kernel() {
    __shared__ int sums[1024];
    const int T = 1024;
    int t = threadIdx.x;
    const int chunk = (NN + T - 1) / T;
    int start = t * chunk;
    int end = min(start + chunk, NN);
    int s = 0;
    for (int i = start; i < end; i++) s += g_deg[i] + 1;
    sums[t] = s;
    __syncthreads();
    for (int off = 1; off < T; off <<= 1) {
        int v = 0;
        if (t >= off) v = sums[t - off];
        __syncthreads();
        if (t >= off) sums[t] += v;
        __syncthreads();
    }
    int base = (t == 0) ? 0 : sums[t - 1];
    for (int i = start; i < end; i++) {
        g_rowoff[i] = base;
        g_cur[i] = base;
        base += g_deg[i] + 1;
        g_deg[i] = 0;
    }
    if (t == 0) g_rowoff[NN] = sums[T - 1];
}

__global__ void scatter_kernel(const int* __restrict__ src, const int* __restrict__ dst) {
    int i = blockIdx.x * blockDim.x + threadIdx.x;
    if (i < EE) {
        int d = dst[i];
        int pos = atomicAdd(&g_cur[d], 1);
        g_csr[pos] = src[i];
    } else if (i < EE + NN) {
        int n = i - EE;
        int pos = atomicAdd(&g_cur[n], 1);
        g_csr[pos] = n;
    }
}

// group boundaries from sorted batch
__global__ void gbound_kernel(const int* __restrict__ batch) {
    int i = blockIdx.x * blockDim.x + threadIdx.x;
    if (i >= NN) return;
    int b = batch[i];
    int prev = (i == 0) ? -1 : batch[i - 1];
    for (int g = prev + 1; g <= b; g++) g_goff[g] = i;
    if (i == NN - 1) {
        for (int g = b + 1; g <= GG; g++) g_goff[g] = NN;
    }
}

// ---------------- GEMM + fused alpha ----------------
__global__ __launch_bounds__(256) void gemm_kernel(
    const float* __restrict__ X, const float* __restrict__ W,
    float* __restrict__ Out, int nrows, int K,
    const float* __restrict__ a_src, const float* __restrict__ a_dst)
{
    __shared__ float Ws[64 * 128];
    __shared__ float xs[32 * 68];
    int tid = threadIdx.x;
    int ty = tid >> 3;
    int tx = tid & 7;
    int row0 = blockIdx.x * 32;
    int row = row0 + ty;

    unsigned long long accu[8];
#pragma unroll
    for (int i = 0; i < 8; i++) accu[i] = 0ull;

    for (int k0 = 0; k0 < K; k0 += 64) {
        const float4* Wg = (const float4*)(W + k0 * 128);
        float4* Wsv = (float4*)Ws;
        for (int i = tid; i < 64 * 128 / 4; i += 256) Wsv[i] = Wg[i];
        for (int i = tid; i < 32 * 64; i += 256) {
            int r = i >> 6, k = i & 63;
            int gr = row0 + r;
            xs[r * 68 + k] = (gr < nrows) ? X[gr * K + k0 + k] : 0.0f;
        }
        __syncthreads();
#pragma unroll 4
        for (int k = 0; k < 64; k++) {
            float xv = xs[ty * 68 + k];
            unsigned long long xp;
            asm("mov.b64 %0, {%1, %1};" : "=l"(xp) : "r"(__float_as_int(xv)));
            const float* wr = Ws + k * 128 + tx * 4;
#pragma unroll
            for (int i = 0; i < 4; i++) {
                ulonglong2 w2 = *(const ulonglong2*)(wr + i * 32);
                FFMA2(accu[2 * i],     xp, w2.x, accu[2 * i]);
                FFMA2(accu[2 * i + 1], xp, w2.y, accu[2 * i + 1]);
            }
        }
        __syncthreads();
    }

    float as4[4], ad4[4];
#pragma unroll
    for (int i = 0; i < 4; i++) {
        float2 lo = *(float2*)&accu[2 * i];
        float2 hi = *(float2*)&accu[2 * i + 1];
        int col = i * 32 + tx * 4;
        float4 av = *(const float4*)(a_src + col);
        float4 dv = *(const float4*)(a_dst + col);
        float s1 = lo.x * av.x + lo.y * av.y + hi.x * av.z + hi.y * av.w;
        float s2 = lo.x * dv.x + lo.y * dv.y + hi.x * dv.z + hi.y * dv.w;
#pragma unroll
        for (int off = 4; off; off >>= 1) {
            s1 += __shfl_xor_sync(0xffffffffu, s1, off);
            s2 += __shfl_xor_sync(0xffffffffu, s2, off);
        }
        as4[i] = s1; ad4[i] = s2;
    }
    if (row < nrows) {
        if (tx == 0) {
            *(float4*)&g_as[row * 4] = make_float4(as4[0], as4[1], as4[2], as4[3]);
            *(float4*)&g_ad[row * 4] = make_float4(ad4[0], ad4[1], ad4[2], ad4[3]);
        }
        ulonglong2* o = (ulonglong2*)(Out + row * 128);
#pragma unroll
        for (int i = 0; i < 4; i++) o[i * 8 + tx] = make_ulonglong2(accu[2 * i], accu[2 * i + 1]);
    }
}

// ---------------- aggregation: one warp per dst node, two-pass softmax ----------------
// j-loop unrolled x8: 8 independent LDG.128 in flight per lane.
__global__ __launch_bounds__(256) void agg_kernel(
    const float* __restrict__ hbuf, const float* __restrict__ bias,
    float* __restrict__ outbuf)
{
    __shared__ int    s_src[8][32];
    __shared__ float4 s_p[8][32];

    int wi = threadIdx.x >> 5;
    int n = (blockIdx.x * blockDim.x + threadIdx.x) >> 5;
    if (n >= NN) return;
    int lane = threadIdx.x & 31;
    int head = lane >> 3;
    int col = head * 32 + (lane & 7) * 4;

    float4 adv = *(const float4*)&g_ad[n * 4];
    int beg = g_rowoff[n], end = g_rowoff[n + 1];

    // pass 1: per-head max (edge-parallel)
    float4 mx = make_float4(-1e30f, -1e30f, -1e30f, -1e30f);
    for (int p = beg + lane; p < end; p += 32) {
        int s = __ldg(&g_csr[p]);
        float4 a = __ldg((const float4*)&g_as[s * 4]);
        float e;
        e = a.x + adv.x; mx.x = fmaxf(mx.x, fmaxf(e, NEG * e));
        e = a.y + adv.y; mx.y = fmaxf(mx.y, fmaxf(e, NEG * e));
        e = a.z + adv.z; mx.z = fmaxf(mx.z, fmaxf(e, NEG * e));
        e = a.w + adv.w; mx.w = fmaxf(mx.w, fmaxf(e, NEG * e));
    }
#pragma unroll
    for (int off = 16; off; off >>= 1) {
        mx.x = fmaxf(mx.x, __shfl_xor_sync(0xffffffffu, mx.x, off));
        mx.y = fmaxf(mx.y, __shfl_xor_sync(0xffffffffu, mx.y, off));
        mx.z = fmaxf(mx.z, __shfl_xor_sync(0xffffffffu, mx.z, off));
        mx.w = fmaxf(mx.w, __shfl_xor_sync(0xffffffffu, mx.w, off));
    }

    // pass 2
    float4 a0 = make_float4(0.f, 0.f, 0.f, 0.f);
    float4 a1 = a0;
    float4 ss = a0;

    for (int p0 = beg; p0 < end; p0 += 32) {
        int cnt = min(32, end - p0);
        float4 pv = make_float4(0.f, 0.f, 0.f, 0.f);
        int s = 0;
        if (lane < cnt) {
            s = __ldg(&g_csr[p0 + lane]);
            float4 a = __ldg((const float4*)&g_as[s * 4]);
            float e;
            e = a.x + adv.x; e = fmaxf(e, NEG * e); pv.x = __expf(e - mx.x);
            e = a.y + adv.y; e = fmaxf(e, NEG * e); pv.y = __expf(e - mx.y);
            e = a.z + adv.z; e = fmaxf(e, NEG * e); pv.z = __expf(e - mx.z);
            e = a.w + adv.w; e = fmaxf(e, NEG * e); pv.w = __expf(e - mx.w);
            ss.x += pv.x; ss.y += pv.y; ss.z += pv.z; ss.w += pv.w;
        }
        s_src[wi][lane] = s;
        s_p[wi][lane] = pv;
        __syncwarp();
        int j = 0;
        for (; j + 8 <= cnt; j += 8) {
            int sj[8];
#pragma unroll
            for (int u = 0; u < 8; u++) sj[u] = s_src[wi][j + u];
            float4 hv[8];
#pragma unroll
            for (int u = 0; u < 8; u++)
                hv[u] = __ldg((const float4*)(hbuf + sj[u] * 128 + col));
            float pw[8];
#pragma unroll
            for (int u = 0; u < 8; u++)
                pw[u] = ((const float*)&s_p[wi][j + u])[head];
#pragma unroll
            for (int u = 0; u < 8; u += 2) {
                a0.x = fmaf(pw[u], hv[u].x, a0.x);
                a0.y = fmaf(pw[u], hv[u].y, a0.y);
                a0.z = fmaf(pw[u], hv[u].z, a0.z);
                a0.w = fmaf(pw[u], hv[u].w, a0.w);
                a1.x = fmaf(pw[u + 1], hv[u + 1].x, a1.x);
                a1.y = fmaf(pw[u + 1], hv[u + 1].y, a1.y);
                a1.z = fmaf(pw[u + 1], hv[u + 1].z, a1.z);
                a1.w = fmaf(pw[u + 1], hv[u + 1].w, a1.w);
            }
        }
        for (; j < cnt; j++) {
            int sj = s_src[wi][j];
            float pj = ((const float*)&s_p[wi][j])[head];
            float4 hv = __ldg((const float4*)(hbuf + sj * 128 + col));
            a0.x = fmaf(pj, hv.x, a0.x); a0.y = fmaf(pj, hv.y, a0.y);
            a0.z = fmaf(pj, hv.z, a0.z); a0.w = fmaf(pj, hv.w, a0.w);
        }
        __syncwarp();
    }

    float4 acc;
    acc.x = a0.x + a1.x;
    acc.y = a0.y + a1.y;
    acc.z = a0.z + a1.z;
    acc.w = a0.w + a1.w;

#pragma unroll
    for (int off = 16; off; off >>= 1) {
        ss.x += __shfl_xor_sync(0xffffffffu, ss.x, off);
        ss.y += __shfl_xor_sync(0xffffffffu, ss.y, off);
        ss.z += __shfl_xor_sync(0xffffffffu, ss.z, off);
        ss.w += __shfl_xor_sync(0xffffffffu, ss.w, off);
    }
    float sh = (head == 0) ? ss.x : (head == 1) ? ss.y : (head == 2) ? ss.z : ss.w;
    float inv = 1.0f / (sh + 1e-16f);

    float4 b = *(const float4*)(bias + col);
    float4 o;
    o.x = acc.x * inv + b.x; o.x = fmaxf(o.x, NEG * o.x);
    o.y = acc.y * inv + b.y; o.y = fmaxf(o.y, NEG * o.y);
    o.z = acc.z * inv + b.z; o.z = fmaxf(o.z, NEG * o.z);
    o.w = acc.w * inv + b.w; o.w = fmaxf(o.w, NEG * o.w);
    *(float4*)(outbuf + n * 128 + col) = o;
}

// ---------------- pooling: segmented over sorted batch ----------------
__global__ __launch_bounds__(512) void pool_kernel(const float* __restrict__ y) {
    __shared__ float sh[3][128];
    int g = blockIdx.x;
    int s = g_goff[g], e = g_goff[g + 1];
    int c = threadIdx.x & 127;
    int r = threadIdx.x >> 7;
    float acc = 0.f;
    for (int i = s + r; i < e; i += 4) acc += y[i * 128 + c];
    if (r) sh[r - 1][c] = acc;
    __syncthreads();
    if (!r) g_pool[g * 128 + c] = ((acc + sh[0][c]) + (sh[1][c] + sh[2][c]));
}

// ---------------- head ----------------
__global__ void head_kernel(const float* __restrict__ fc_w, const float* __restrict__ fc_b,
                            const float* __restrict__ bn_g, const float* __restrict__ bn_b,
                            float* __restrict__ out)
{
    int g = blockIdx.x;
    int l = threadIdx.x;
    const float* pr = g_pool + g * HID;
    float s = 0.f;
#pragma unroll 8
    for (int k = 0; k < HID; k++) s = fmaf(pr[k], fc_w[k * LAT + l], s);
    s += fc_b[l];
    const float inv = 0.999995000037499688f;  // 1/sqrt(1 + 1e-5)
    out[g * LAT + l] = bn_g[l] * s * inv + bn_b[l];
}

// ---------------- launch ----------------
extern "C" void kernel_launch(void* const* d_in, const int* in_sizes, int n_in,
                              void* d_out, int out_size)
{
    const float* x       = (const float*)d_in[0];
    const int*   eidx    = (const int*)  d_in[1];
    const int*   batch   = (const int*)  d_in[2];
    const float* W0      = (const float*)d_in[3];
    const float* a_src0  = (const float*)d_in[4];
    const float* a_dst0  = (const float*)d_in[5];
    const float* b0      = (const float*)d_in[6];
    const float* W1      = (const float*)d_in[7];
    const float* a_src1  = (const float*)d_in[8];
    const float* a_dst1  = (const float*)d_in[9];
    const float* b1      = (const float*)d_in[10];
    const float* W2      = (const float*)d_in[11];
    const float* a_src2  = (const float*)d_in[12];
    const float* a_dst2  = (const float*)d_in[13];
    const float* b2      = (const float*)d_in[14];
    const float* fc_w    = (const float*)d_in[15];
    const float* fc_b    = (const float*)d_in[16];
    const float* bn_g    = (const float*)d_in[17];
    const float* bn_b    = (const float*)d_in[18];
    float* out = (float*)d_out;

    const int* src = eidx;
    const int* dst = eidx + EE;

    float *ph, *py;
    cudaGetSymbolAddress((void**)&ph, g_h);
    cudaGetSymbolAddress((void**)&py, g_y);

    // CSR build: g_deg is zero on entry (zero-init + scan restores it)
    hist_kernel<<<(EE + 255) / 256, 256>>>(dst);
    scan_kernel<<<1, 1024>>>();
    scatter_kernel<<<(EE + NN + 255) / 256, 256>>>(src, dst);

    const int gemm_grid = (NN + 31) / 32;
    const int warp_grid = (NN + 7) / 8;

    gemm_kernel<<<gemm_grid, 256>>>(x, W0, ph, NN, 64, a_src0, a_dst0);
    agg_kernel<<<warp_grid, 256>>>(ph, b0, py);

    gemm_kernel<<<gemm_grid, 256>>>(py, W1, ph, NN, 128, a_src1, a_dst1);
    agg_kernel<<<warp_grid, 256>>>(ph, b1, py);

    gemm_kernel<<<gemm_grid, 256>>>(py, W2, ph, NN, 128, a_src2, a_dst2);
    agg_kernel<<<warp_grid, 256>>>(ph, b2, py);

    gbound_kernel<<<(NN + 255) / 256, 256>>>(batch);
    pool_kernel<<<GG, 512>>>(py);
    head_kernel<<<GG, LAT>>>(fc_w, fc_b, bn_g, bn_b, out);
}

// round 5
// speedup vs baseline: 1.4373x; 1.4373x over previous
#include <cuda_runtime.h>
#include <math.h>

#define NN 50000
#define EE 800000
#define HID 128
#define GG 128
#define LAT 32
#define NEG 0.2f

// ---------------- scratch (static device memory; zero-initialized) ----------------
__device__ float g_h[NN * HID];
__device__ float g_y[NN * HID];
__device__ float g_as[NN * 4];
__device__ float g_ad[NN * 4];
__device__ int   g_deg[NN];          // invariant: zero before/after each launch
__device__ int   g_rowoff[NN + 1];
__device__ int   g_cur[NN];
__device__ int   g_csr[EE + NN];
__device__ int   g_goff[GG + 1];
__device__ float g_pool[GG * HID];

#define FFMA2(d, a, b, c) \
    asm("fma.rn.f32x2 %0, %1, %2, %3;" : "=l"(d) : "l"(a), "l"(b), "l"(c))

// ---------------- CSR build ----------------
__global__ void hist_kernel(const int* __restrict__ dst) {
    int i = blockIdx.x * blockDim.x + threadIdx.x;
    if (i < EE) atomicAdd(&g_deg[dst[i]], 1);
}

// reads g_deg (+1 self loop), builds rowoff/cur, and RE-ZEROES g_deg.
__global__ void scan_kernel() {
    __shared__ int sums[1024];
    const int T = 1024;
    int t = threadIdx.x;
    const int chunk = (NN + T - 1) / T;
    int start = t * chunk;
    int end = min(start + chunk, NN);
    int s = 0;
    for (int i = start; i < end; i++) s += g_deg[i] + 1;
    sums[t] = s;
    __syncthreads();
    for (int off = 1; off < T; off <<= 1) {
        int v = 0;
        if (t >= off) v = sums[t - off];
        __syncthreads();
        if (t >= off) sums[t] += v;
        __syncthreads();
    }
    int base = (t == 0) ? 0 : sums[t - 1];
    for (int i = start; i < end; i++) {
        g_rowoff[i] = base;
        g_cur[i] = base;
        base += g_deg[i] + 1;
        g_deg[i] = 0;
    }
    if (t == 0) g_rowoff[NN] = sums[T - 1];
}

__global__ void scatter_kernel(const int* __restrict__ src, const int* __restrict__ dst) {
    int i = blockIdx.x * blockDim.x + threadIdx.x;
    if (i < EE) {
        int d = dst[i];
        int pos = atomicAdd(&g_cur[d], 1);
        g_csr[pos] = src[i];
    } else if (i < EE + NN) {
        int n = i - EE;
        int pos = atomicAdd(&g_cur[n], 1);
        g_csr[pos] = n;
    }
}

__global__ void gbound_kernel(const int* __restrict__ batch) {
    int i = blockIdx.x * blockDim.x + threadIdx.x;
    if (i >= NN) return;
    int b = batch[i];
    int prev = (i == 0) ? -1 : batch[i - 1];
    for (int g = prev + 1; g <= b; g++) g_goff[g] = i;
    if (i == NN - 1) {
        for (int g = b + 1; g <= GG; g++) g_goff[g] = NN;
    }
}

// ---------------- GEMM + fused alpha (register-blocked 4x16 per thread) ----------
// Tile: 128 rows x 128 cols per block, 256 threads.
// ty = tid>>3 (0..31): rows ty*4..+3.  tx = tid&7: cols tx*4 + i*32, i=0..3.
// x staged k-major transposed (xsT[k][row]) so 1 LDS.128 fetches 4 rows.
__global__ __launch_bounds__(256, 2) void gemm_kernel(
    const float* __restrict__ X, const float* __restrict__ W,
    float* __restrict__ Out, int nrows, int K,
    const float* __restrict__ a_src, const float* __restrict__ a_dst)
{
    __shared__ float Ws[32 * 128];     // 16 KB
    __shared__ float xsT[32 * 132];    // 16.5 KB, stride 132 (528B = 33*16, 16B-aligned rows)
    int tid = threadIdx.x;
    int ty = tid >> 3;
    int tx = tid & 7;
    int row0 = blockIdx.x * 128;

    unsigned long long acc[4][8];      // [r][i*2+p]
#pragma unroll
    for (int r = 0; r < 4; r++)
#pragma unroll
        for (int j = 0; j < 8; j++) acc[r][j] = 0ull;

    int lrow = tid & 127;              // loader row within tile
    int half = tid >> 7;               // 0/1: k-subrange half*16..+15
    int grow = row0 + lrow;

    for (int k0 = 0; k0 < K; k0 += 32) {
        // W chunk [32][128]
        const float4* Wg = (const float4*)(W + k0 * 128);
        float4* Wsv = (float4*)Ws;
#pragma unroll
        for (int i = 0; i < 4; i++) Wsv[tid + i * 256] = Wg[tid + i * 256];
        // x chunk transposed: thread loads X[grow][k0+half*16 .. +15]
        {
            float4 v[4];
            if (grow < nrows) {
                const float4* xr = (const float4*)(X + (size_t)grow * K + k0 + half * 16);
#pragma unroll
                for (int j = 0; j < 4; j++) v[j] = __ldg(xr + j);
            } else {
#pragma unroll
                for (int j = 0; j < 4; j++) v[j] = make_float4(0.f, 0.f, 0.f, 0.f);
            }
#pragma unroll
            for (int j = 0; j < 4; j++) {
                int kk = half * 16 + j * 4;
                xsT[(kk + 0) * 132 + lrow] = v[j].x;
                xsT[(kk + 1) * 132 + lrow] = v[j].y;
                xsT[(kk + 2) * 132 + lrow] = v[j].z;
                xsT[(kk + 3) * 132 + lrow] = v[j].w;
            }
        }
        __syncthreads();
#pragma unroll 8
        for (int k = 0; k < 32; k++) {
            float4 xv = *(const float4*)&xsT[k * 132 + ty * 4];
            unsigned long long xp[4];
            asm("mov.b64 %0, {%1, %1};" : "=l"(xp[0]) : "r"(__float_as_int(xv.x)));
            asm("mov.b64 %0, {%1, %1};" : "=l"(xp[1]) : "r"(__float_as_int(xv.y)));
            asm("mov.b64 %0, {%1, %1};" : "=l"(xp[2]) : "r"(__float_as_int(xv.z)));
            asm("mov.b64 %0, {%1, %1};" : "=l"(xp[3]) : "r"(__float_as_int(xv.w)));
            ulonglong2 w[4];
            const float* wr = Ws + k * 128 + tx * 4;
#pragma unroll
            for (int i = 0; i < 4; i++) w[i] = *(const ulonglong2*)(wr + i * 32);
#pragma unroll
            for (int r = 0; r < 4; r++) {
#pragma unroll
                for (int i = 0; i < 4; i++) {
                    FFMA2(acc[r][2 * i],     xp[r], w[i].x, acc[r][2 * i]);
                    FFMA2(acc[r][2 * i + 1], xp[r], w[i].y, acc[r][2 * i + 1]);
                }
            }
        }
        __syncthreads();
    }

    // fused alpha + stores; 8-lane (same ty) reduction per row/head
#pragma unroll
    for (int r = 0; r < 4; r++) {
        int row = row0 + ty * 4 + r;
        float as4[4], ad4[4];
#pragma unroll
        for (int i = 0; i < 4; i++) {
            float2 lo = *(float2*)&acc[r][2 * i];
            float2 hi = *(float2*)&acc[r][2 * i + 1];
            int col = i * 32 + tx * 4;
            float4 av = *(const float4*)(a_src + col);
            float4 dv = *(const float4*)(a_dst + col);
            float s1 = lo.x * av.x + lo.y * av.y + hi.x * av.z + hi.y * av.w;
            float s2 = lo.x * dv.x + lo.y * dv.y + hi.x * dv.z + hi.y * dv.w;
#pragma unroll
            for (int off = 4; off; off >>= 1) {
                s1 += __shfl_xor_sync(0xffffffffu, s1, off);
                s2 += __shfl_xor_sync(0xffffffffu, s2, off);
            }
            as4[i] = s1; ad4[i] = s2;
        }
        if (row < nrows) {
            if (tx == 0) {
                *(float4*)&g_as[row * 4] = make_float4(as4[0], as4[1], as4[2], as4[3]);
                *(float4*)&g_ad[row * 4] = make_float4(ad4[0], ad4[1], ad4[2], ad4[3]);
            }
            ulonglong2* o = (ulonglong2*)(Out + (size_t)row * 128);
#pragma unroll
            for (int i = 0; i < 4; i++)
                o[i * 8 + tx] = make_ulonglong2(acc[r][2 * i], acc[r][2 * i + 1]);
        }
    }
}

// ---------------- aggregation: one warp per dst node, two-pass softmax (R2 form) --
__global__ __launch_bounds__(256) void agg_kernel(
    const float* __restrict__ hbuf, const float* __restrict__ bias,
    float* __restrict__ outbuf)
{
    __shared__ int    s_src[8][32];
    __shared__ float4 s_p[8][32];

    int wi = threadIdx.x >> 5;
    int n = (blockIdx.x * blockDim.x + threadIdx.x) >> 5;
    if (n >= NN) return;
    int lane = threadIdx.x & 31;
    int head = lane >> 3;
    int col = head * 32 + (lane & 7) * 4;

    float4 adv = *(const float4*)&g_ad[n * 4];
    int beg = g_rowoff[n], end = g_rowoff[n + 1];

    float4 mx = make_float4(-1e30f, -1e30f, -1e30f, -1e30f);
    for (int p = beg + lane; p < end; p += 32) {
        int s = __ldg(&g_csr[p]);
        float4 a = __ldg((const float4*)&g_as[s * 4]);
        float e;
        e = a.x + adv.x; mx.x = fmaxf(mx.x, fmaxf(e, NEG * e));
        e = a.y + adv.y; mx.y = fmaxf(mx.y, fmaxf(e, NEG * e));
        e = a.z + adv.z; mx.z = fmaxf(mx.z, fmaxf(e, NEG * e));
        e = a.w + adv.w; mx.w = fmaxf(mx.w, fmaxf(e, NEG * e));
    }
#pragma unroll
    for (int off = 16; off; off >>= 1) {
        mx.x = fmaxf(mx.x, __shfl_xor_sync(0xffffffffu, mx.x, off));
        mx.y = fmaxf(mx.y, __shfl_xor_sync(0xffffffffu, mx.y, off));
        mx.z = fmaxf(mx.z, __shfl_xor_sync(0xffffffffu, mx.z, off));
        mx.w = fmaxf(mx.w, __shfl_xor_sync(0xffffffffu, mx.w, off));
    }

    float4 acc = make_float4(0.f, 0.f, 0.f, 0.f);
    float4 ss  = acc;

    for (int p0 = beg; p0 < end; p0 += 32) {
        int cnt = min(32, end - p0);
        float4 pv = make_float4(0.f, 0.f, 0.f, 0.f);
        int s = 0;
        if (lane < cnt) {
            s = __ldg(&g_csr[p0 + lane]);
            float4 a = __ldg((const float4*)&g_as[s * 4]);
            float e;
            e = a.x + adv.x; e = fmaxf(e, NEG * e); pv.x = __expf(e - mx.x);
            e = a.y + adv.y; e = fmaxf(e, NEG * e); pv.y = __expf(e - mx.y);
            e = a.z + adv.z; e = fmaxf(e, NEG * e); pv.z = __expf(e - mx.z);
            e = a.w + adv.w; e = fmaxf(e, NEG * e); pv.w = __expf(e - mx.w);
            ss.x += pv.x; ss.y += pv.y; ss.z += pv.z; ss.w += pv.w;
        }
        s_src[wi][lane] = s;
        s_p[wi][lane] = pv;
        __syncwarp();
        for (int j = 0; j < cnt; j++) {
            int sj = s_src[wi][j];
            float pj = ((const float*)&s_p[wi][j])[head];
            float4 hv = __ldg((const float4*)(hbuf + sj * 128 + col));
            acc.x = fmaf(pj, hv.x, acc.x);
            acc.y = fmaf(pj, hv.y, acc.y);
            acc.z = fmaf(pj, hv.z, acc.z);
            acc.w = fmaf(pj, hv.w, acc.w);
        }
        __syncwarp();
    }

#pragma unroll
    for (int off = 16; off; off >>= 1) {
        ss.x += __shfl_xor_sync(0xffffffffu, ss.x, off);
        ss.y += __shfl_xor_sync(0xffffffffu, ss.y, off);
        ss.z += __shfl_xor_sync(0xffffffffu, ss.z, off);
        ss.w += __shfl_xor_sync(0xffffffffu, ss.w, off);
    }
    float sh = (head == 0) ? ss.x : (head == 1) ? ss.y : (head == 2) ? ss.z : ss.w;
    float inv = 1.0f / (sh + 1e-16f);

    float4 b = *(const float4*)(bias + col);
    float4 o;
    o.x = acc.x * inv + b.x; o.x = fmaxf(o.x, NEG * o.x);
    o.y = acc.y * inv + b.y; o.y = fmaxf(o.y, NEG * o.y);
    o.z = acc.z * inv + b.z; o.z = fmaxf(o.z, NEG * o.z);
    o.w = acc.w * inv + b.w; o.w = fmaxf(o.w, NEG * o.w);
    *(float4*)(outbuf + n * 128 + col) = o;
}

// ---------------- pooling: segmented over sorted batch ----------------
__global__ __launch_bounds__(512) void pool_kernel(const float* __restrict__ y) {
    __shared__ float sh[3][128];
    int g = blockIdx.x;
    int s = g_goff[g], e = g_goff[g + 1];
    int c = threadIdx.x & 127;
    int r = threadIdx.x >> 7;
    float acc = 0.f;
    for (int i = s + r; i < e; i += 4) acc += y[i * 128 + c];
    if (r) sh[r - 1][c] = acc;
    __syncthreads();
    if (!r) g_pool[g * 128 + c] = ((acc + sh[0][c]) + (sh[1][c] + sh[2][c]));
}

// ---------------- head ----------------
__global__ void head_kernel(const float* __restrict__ fc_w, const float* __restrict__ fc_b,
                            const float* __restrict__ bn_g, const float* __restrict__ bn_b,
                            float* __restrict__ out)
{
    int g = blockIdx.x;
    int l = threadIdx.x;
    const float* pr = g_pool + g * HID;
    float s = 0.f;
#pragma unroll 8
    for (int k = 0; k < HID; k++) s = fmaf(pr[k], fc_w[k * LAT + l], s);
    s += fc_b[l];
    const float inv = 0.999995000037499688f;  // 1/sqrt(1 + 1e-5)
    out[g * LAT + l] = bn_g[l] * s * inv + bn_b[l];
}

// ---------------- launch ----------------
extern "C" void kernel_launch(void* const* d_in, const int* in_sizes, int n_in,
                              void* d_out, int out_size)
{
    const float* x       = (const float*)d_in[0];
    const int*   eidx    = (const int*)  d_in[1];
    const int*   batch   = (const int*)  d_in[2];
    const float* W0      = (const float*)d_in[3];
    const float* a_src0  = (const float*)d_in[4];
    const float* a_dst0  = (const float*)d_in[5];
    const float* b0      = (const float*)d_in[6];
    const float* W1      = (const float*)d_in[7];
    const float* a_src1  = (const float*)d_in[8];
    const float* a_dst1  = (const float*)d_in[9];
    const float* b1      = (const float*)d_in[10];
    const float* W2      = (const float*)d_in[11];
    const float* a_src2  = (const float*)d_in[12];
    const float* a_dst2  = (const float*)d_in[13];
    const float* b2      = (const float*)d_in[14];
    const float* fc_w    = (const float*)d_in[15];
    const float* fc_b    = (const float*)d_in[16];
    const float* bn_g    = (const float*)d_in[17];
    const float* bn_b    = (const float*)d_in[18];
    float* out = (float*)d_out;

    const int* src = eidx;
    const int* dst = eidx + EE;

    float *ph, *py;
    cudaGetSymbolAddress((void**)&ph, g_h);
    cudaGetSymbolAddress((void**)&py, g_y);

    hist_kernel<<<(EE + 255) / 256, 256>>>(dst);
    scan_kernel<<<1, 1024>>>();
    scatter_kernel<<<(EE + NN + 255) / 256, 256>>>(src, dst);

    const int gemm_grid = (NN + 127) / 128;
    const int warp_grid = (NN + 7) / 8;

    gemm_kernel<<<gemm_grid, 256>>>(x, W0, ph, NN, 64, a_src0, a_dst0);
    agg_kernel<<<warp_grid, 256>>>(ph, b0, py);

    gemm_kernel<<<gemm_grid, 256>>>(py, W1, ph, NN, 128, a_src1, a_dst1);
    agg_kernel<<<warp_grid, 256>>>(ph, b1, py);

    gemm_kernel<<<gemm_grid, 256>>>(py, W2, ph, NN, 128, a_src2, a_dst2);
    agg_kernel<<<warp_grid, 256>>>(ph, b2, py);

    gbound_kernel<<<(NN + 255) / 256, 256>>>(batch);
    pool_kernel<<<GG, 512>>>(py);
    head_kernel<<<GG, LAT>>>(fc_w, fc_b, bn_g, bn_b, out);
}

// round 6
// speedup vs baseline: 1.4759x; 1.0269x over previous
#include <cuda_runtime.h>
#include <math.h>

#define NN 50000
#define EE 800000
#define HID 128
#define GG 128
#define LAT 32
#define NEG 0.2f

// ---------------- scratch (static device memory; zero-initialized) ----------------
__device__ float g_h[NN * HID];
__device__ float g_y[NN * HID];
__device__ float g_as[NN * 4];
__device__ float g_ad[NN * 4];
__device__ int   g_deg[NN];          // invariant: zero before/after each launch
__device__ int   g_rowoff[NN + 1];
__device__ int   g_cur[NN];
__device__ int   g_csr[EE + NN];
__device__ int   g_goff[GG + 1];
__device__ float g_pool[GG * HID];

#define FFMA2(d, a, b, c) \
    asm("fma.rn.f32x2 %0, %1, %2, %3;" : "=l"(d) : "l"(a), "l"(b), "l"(c))

#define CP16(dst, src, n) \
    asm volatile("cp.async.ca.shared.global [%0], [%1], 16, %2;" \
                 :: "r"(dst), "l"(src), "r"(n))
#define CP_COMMIT() asm volatile("cp.async.commit_group;")
#define CP_WAIT1()  asm volatile("cp.async.wait_group 1;")
#define CP_WAIT0()  asm volatile("cp.async.wait_group 0;")

// ---------------- CSR build ----------------
__global__ void hist_kernel(const int* __restrict__ dst) {
    int i = blockIdx.x * blockDim.x + threadIdx.x;
    if (i < EE) atomicAdd(&g_deg[dst[i]], 1);
}

// reads g_deg (+1 self loop), builds rowoff/cur, and RE-ZEROES g_deg.
__global__ void scan_kernel() {
    __shared__ int sums[1024];
    const int T = 1024;
    int t = threadIdx.x;
    const int chunk = (NN + T - 1) / T;
    int start = t * chunk;
    int end = min(start + chunk, NN);
    int s = 0;
    for (int i = start; i < end; i++) s += g_deg[i] + 1;
    sums[t] = s;
    __syncthreads();
    for (int off = 1; off < T; off <<= 1) {
        int v = 0;
        if (t >= off) v = sums[t - off];
        __syncthreads();
        if (t >= off) sums[t] += v;
        __syncthreads();
    }
    int base = (t == 0) ? 0 : sums[t - 1];
    for (int i = start; i < end; i++) {
        g_rowoff[i] = base;
        g_cur[i] = base;
        base += g_deg[i] + 1;
        g_deg[i] = 0;
    }
    if (t == 0) g_rowoff[NN] = sums[T - 1];
}

__global__ void scatter_kernel(const int* __restrict__ src, const int* __restrict__ dst) {
    int i = blockIdx.x * blockDim.x + threadIdx.x;
    if (i < EE) {
        int d = dst[i];
        int pos = atomicAdd(&g_cur[d], 1);
        g_csr[pos] = src[i];
    } else if (i < EE + NN) {
        int n = i - EE;
        int pos = atomicAdd(&g_cur[n], 1);
        g_csr[pos] = n;
    }
}

__global__ void gbound_kernel(const int* __restrict__ batch) {
    int i = blockIdx.x * blockDim.x + threadIdx.x;
    if (i >= NN) return;
    int b = batch[i];
    int prev = (i == 0) ? -1 : batch[i - 1];
    for (int g = prev + 1; g <= b; g++) g_goff[g] = i;
    if (i == NN - 1) {
        for (int g = b + 1; g <= GG; g++) g_goff[g] = NN;
    }
}

// ---------------- GEMM + fused alpha, cp.async double-buffered ----------------
// Tile: 128 rows x 128 cols, 256 threads, 4 rows x 16 cols per thread.
// K chunked by 16, 2-stage cp.async pipeline.
// xs[row][k] stride 20 words (80B, 16B-aligned rows). Ws[k][c] stride 128.
#define XS_STR 20
__global__ __launch_bounds__(256, 2) void gemm_kernel(
    const float* __restrict__ X, const float* __restrict__ W,
    float* __restrict__ Out, int nrows, int K,
    const float* __restrict__ a_src, const float* __restrict__ a_dst)
{
    __shared__ float Ws[2][16 * 128];       // 2 x 8 KB
    __shared__ float xs[2][128 * XS_STR];   // 2 x 10 KB
    int tid = threadIdx.x;
    int ty = tid >> 3;
    int tx = tid & 7;
    int row0 = blockIdx.x * 128;

    // loader mapping: thread handles row=tid>>1, k-half=tid&1 (8 floats = 2x16B)
    int lrow = tid >> 1;
    int lhalf = tid & 1;
    int grow = row0 + lrow;
    int xsz = (grow < nrows) ? 16 : 0;   // zfill OOB rows
    const float* xsrc0 = X + (size_t)grow * K + lhalf * 8;
    unsigned xdst0 = (unsigned)__cvta_generic_to_shared(&xs[0][lrow * XS_STR + lhalf * 8]);
    unsigned xdst1 = (unsigned)__cvta_generic_to_shared(&xs[1][lrow * XS_STR + lhalf * 8]);
    unsigned wdst0 = (unsigned)__cvta_generic_to_shared(&Ws[0][0]);
    unsigned wdst1 = (unsigned)__cvta_generic_to_shared(&Ws[1][0]);

    unsigned long long acc[4][8];
#pragma unroll
    for (int r = 0; r < 4; r++)
#pragma unroll
        for (int j = 0; j < 8; j++) acc[r][j] = 0ull;

    const int NC = K >> 4;

    // prefetch chunk 0
    {
        const float4* Wg = (const float4*)(W);
        CP16(wdst0 + tid * 16, (const void*)(Wg + tid), 16);
        CP16(wdst0 + (tid + 256) * 16, (const void*)(Wg + tid + 256), 16);
        CP16(xdst0,      (const void*)xsrc0,       xsz);
        CP16(xdst0 + 16, (const void*)(xsrc0 + 4), xsz);
        CP_COMMIT();
    }

    for (int c = 0; c < NC; c++) {
        int cb = c & 1;
        if (c + 1 < NC) {
            unsigned wd = (cb ? wdst0 : wdst1);
            unsigned xd = (cb ? xdst0 : xdst1);
            const float4* Wg = (const float4*)(W + (c + 1) * 16 * 128);
            const float* xsrc = xsrc0 + (c + 1) * 16;
            CP16(wd + tid * 16, (const void*)(Wg + tid), 16);
            CP16(wd + (tid + 256) * 16, (const void*)(Wg + tid + 256), 16);
            CP16(xd,      (const void*)xsrc,       xsz);
            CP16(xd + 16, (const void*)(xsrc + 4), xsz);
            CP_COMMIT();
            CP_WAIT1();
        } else {
            CP_WAIT0();
        }
        __syncthreads();

#pragma unroll
        for (int k4 = 0; k4 < 4; k4++) {
            float4 xq[4];
#pragma unroll
            for (int r = 0; r < 4; r++)
                xq[r] = *(const float4*)&xs[cb][(ty * 4 + r) * XS_STR + k4 * 4];
#pragma unroll
            for (int kk = 0; kk < 4; kk++) {
                int k = k4 * 4 + kk;
                unsigned long long xp[4];
                float xr0 = (kk == 0) ? xq[0].x : (kk == 1) ? xq[0].y : (kk == 2) ? xq[0].z : xq[0].w;
                float xr1 = (kk == 0) ? xq[1].x : (kk == 1) ? xq[1].y : (kk == 2) ? xq[1].z : xq[1].w;
                float xr2 = (kk == 0) ? xq[2].x : (kk == 1) ? xq[2].y : (kk == 2) ? xq[2].z : xq[2].w;
                float xr3 = (kk == 0) ? xq[3].x : (kk == 1) ? xq[3].y : (kk == 2) ? xq[3].z : xq[3].w;
                asm("mov.b64 %0, {%1, %1};" : "=l"(xp[0]) : "r"(__float_as_int(xr0)));
                asm("mov.b64 %0, {%1, %1};" : "=l"(xp[1]) : "r"(__float_as_int(xr1)));
                asm("mov.b64 %0, {%1, %1};" : "=l"(xp[2]) : "r"(__float_as_int(xr2)));
                asm("mov.b64 %0, {%1, %1};" : "=l"(xp[3]) : "r"(__float_as_int(xr3)));
                ulonglong2 w[4];
                const float* wr = &Ws[cb][k * 128 + tx * 4];
#pragma unroll
                for (int i = 0; i < 4; i++) w[i] = *(const ulonglong2*)(wr + i * 32);
#pragma unroll
                for (int r = 0; r < 4; r++) {
#pragma unroll
                    for (int i = 0; i < 4; i++) {
                        FFMA2(acc[r][2 * i],     xp[r], w[i].x, acc[r][2 * i]);
                        FFMA2(acc[r][2 * i + 1], xp[r], w[i].y, acc[r][2 * i + 1]);
                    }
                }
            }
        }
        __syncthreads();
    }

    // fused alpha + stores; 8-lane (same ty) reduction per row/head
#pragma unroll
    for (int r = 0; r < 4; r++) {
        int row = row0 + ty * 4 + r;
        float as4[4], ad4[4];
#pragma unroll
        for (int i = 0; i < 4; i++) {
            float2 lo = *(float2*)&acc[r][2 * i];
            float2 hi = *(float2*)&acc[r][2 * i + 1];
            int col = i * 32 + tx * 4;
            float4 av = *(const float4*)(a_src + col);
            float4 dv = *(const float4*)(a_dst + col);
            float s1 = lo.x * av.x + lo.y * av.y + hi.x * av.z + hi.y * av.w;
            float s2 = lo.x * dv.x + lo.y * dv.y + hi.x * dv.z + hi.y * dv.w;
#pragma unroll
            for (int off = 4; off; off >>= 1) {
                s1 += __shfl_xor_sync(0xffffffffu, s1, off);
                s2 += __shfl_xor_sync(0xffffffffu, s2, off);
            }
            as4[i] = s1; ad4[i] = s2;
        }
        if (row < nrows) {
            if (tx == 0) {
                *(float4*)&g_as[row * 4] = make_float4(as4[0], as4[1], as4[2], as4[3]);
                *(float4*)&g_ad[row * 4] = make_float4(ad4[0], ad4[1], ad4[2], ad4[3]);
            }
            ulonglong2* o = (ulonglong2*)(Out + (size_t)row * 128);
#pragma unroll
            for (int i = 0; i < 4; i++)
                o[i * 8 + tx] = make_ulonglong2(acc[r][2 * i], acc[r][2 * i + 1]);
        }
    }
}

// ---------------- aggregation: one warp per dst node, two-pass softmax ----------
__global__ __launch_bounds__(256) void agg_kernel(
    const float* __restrict__ hbuf, const float* __restrict__ bias,
    float* __restrict__ outbuf)
{
    __shared__ int    s_src[8][32];
    __shared__ float4 s_p[8][32];

    int wi = threadIdx.x >> 5;
    int n = (blockIdx.x * blockDim.x + threadIdx.x) >> 5;
    if (n >= NN) return;
    int lane = threadIdx.x & 31;
    int head = lane >> 3;
    int col = head * 32 + (lane & 7) * 4;

    float4 adv = *(const float4*)&g_ad[n * 4];
    int beg = g_rowoff[n], end = g_rowoff[n + 1];

    float4 mx = make_float4(-1e30f, -1e30f, -1e30f, -1e30f);
    for (int p = beg + lane; p < end; p += 32) {
        int s = __ldg(&g_csr[p]);
        float4 a = __ldg((const float4*)&g_as[s * 4]);
        float e;
        e = a.x + adv.x; mx.x = fmaxf(mx.x, fmaxf(e, NEG * e));
        e = a.y + adv.y; mx.y = fmaxf(mx.y, fmaxf(e, NEG * e));
        e = a.z + adv.z; mx.z = fmaxf(mx.z, fmaxf(e, NEG * e));
        e = a.w + adv.w; mx.w = fmaxf(mx.w, fmaxf(e, NEG * e));
    }
#pragma unroll
    for (int off = 16; off; off >>= 1) {
        mx.x = fmaxf(mx.x, __shfl_xor_sync(0xffffffffu, mx.x, off));
        mx.y = fmaxf(mx.y, __shfl_xor_sync(0xffffffffu, mx.y, off));
        mx.z = fmaxf(mx.z, __shfl_xor_sync(0xffffffffu, mx.z, off));
        mx.w = fmaxf(mx.w, __shfl_xor_sync(0xffffffffu, mx.w, off));
    }

    float4 acc = make_float4(0.f, 0.f, 0.f, 0.f);
    float4 ss  = acc;

    for (int p0 = beg; p0 < end; p0 += 32) {
        int cnt = min(32, end - p0);
        float4 pv = make_float4(0.f, 0.f, 0.f, 0.f);
        int s = 0;
        if (lane < cnt) {
            s = __ldg(&g_csr[p0 + lane]);
            float4 a = __ldg((const float4*)&g_as[s * 4]);
            float e;
            e = a.x + adv.x; e = fmaxf(e, NEG * e); pv.x = __expf(e - mx.x);
            e = a.y + adv.y; e = fmaxf(e, NEG * e); pv.y = __expf(e - mx.y);
            e = a.z + adv.z; e = fmaxf(e, NEG * e); pv.z = __expf(e - mx.z);
            e = a.w + adv.w; e = fmaxf(e, NEG * e); pv.w = __expf(e - mx.w);
            ss.x += pv.x; ss.y += pv.y; ss.z += pv.z; ss.w += pv.w;
        }
        s_src[wi][lane] = s;
        s_p[wi][lane] = pv;
        __syncwarp();
        for (int j = 0; j < cnt; j++) {
            int sj = s_src[wi][j];
            float pj = ((const float*)&s_p[wi][j])[head];
            float4 hv = __ldg((const float4*)(hbuf + sj * 128 + col));
            acc.x = fmaf(pj, hv.x, acc.x);
            acc.y = fmaf(pj, hv.y, acc.y);
            acc.z = fmaf(pj, hv.z, acc.z);
            acc.w = fmaf(pj, hv.w, acc.w);
        }
        __syncwarp();
    }

#pragma unroll
    for (int off = 16; off; off >>= 1) {
        ss.x += __shfl_xor_sync(0xffffffffu, ss.x, off);
        ss.y += __shfl_xor_sync(0xffffffffu, ss.y, off);
        ss.z += __shfl_xor_sync(0xffffffffu, ss.z, off);
        ss.w += __shfl_xor_sync(0xffffffffu, ss.w, off);
    }
    float sh = (head == 0) ? ss.x : (head == 1) ? ss.y : (head == 2) ? ss.z : ss.w;
    float inv = 1.0f / (sh + 1e-16f);

    float4 b = *(const float4*)(bias + col);
    float4 o;
    o.x = acc.x * inv + b.x; o.x = fmaxf(o.x, NEG * o.x);
    o.y = acc.y * inv + b.y; o.y = fmaxf(o.y, NEG * o.y);
    o.z = acc.z * inv + b.z; o.z = fmaxf(o.z, NEG * o.z);
    o.w = acc.w * inv + b.w; o.w = fmaxf(o.w, NEG * o.w);
    *(float4*)(outbuf + n * 128 + col) = o;
}

// ---------------- pooling: segmented over sorted batch ----------------
__global__ __launch_bounds__(512) void pool_kernel(const float* __restrict__ y) {
    __shared__ float sh[3][128];
    int g = blockIdx.x;
    int s = g_goff[g], e = g_goff[g + 1];
    int c = threadIdx.x & 127;
    int r = threadIdx.x >> 7;
    float acc = 0.f;
    for (int i = s + r; i < e; i += 4) acc += y[i * 128 + c];
    if (r) sh[r - 1][c] = acc;
    __syncthreads();
    if (!r) g_pool[g * 128 + c] = ((acc + sh[0][c]) + (sh[1][c] + sh[2][c]));
}

// ---------------- head ----------------
__global__ void head_kernel(const float* __restrict__ fc_w, const float* __restrict__ fc_b,
                            const float* __restrict__ bn_g, const float* __restrict__ bn_b,
                            float* __restrict__ out)
{
    int g = blockIdx.x;
    int l = threadIdx.x;
    const float* pr = g_pool + g * HID;
    float s = 0.f;
#pragma unroll 8
    for (int k = 0; k < HID; k++) s = fmaf(pr[k], fc_w[k * LAT + l], s);
    s += fc_b[l];
    const float inv = 0.999995000037499688f;  // 1/sqrt(1 + 1e-5)
    out[g * LAT + l] = bn_g[l] * s * inv + bn_b[l];
}

// ---------------- launch ----------------
extern "C" void kernel_launch(void* const* d_in, const int* in_sizes, int n_in,
                              void* d_out, int out_size)
{
    const float* x       = (const float*)d_in[0];
    const int*   eidx    = (const int*)  d_in[1];
    const int*   batch   = (const int*)  d_in[2];
    const float* W0      = (const float*)d_in[3];
    const float* a_src0  = (const float*)d_in[4];
    const float* a_dst0  = (const float*)d_in[5];
    const float* b0      = (const float*)d_in[6];
    const float* W1      = (const float*)d_in[7];
    const float* a_src1  = (const float*)d_in[8];
    const float* a_dst1  = (const float*)d_in[9];
    const float* b1      = (const float*)d_in[10];
    const float* W2      = (const float*)d_in[11];
    const float* a_src2  = (const float*)d_in[12];
    const float* a_dst2  = (const float*)d_in[13];
    const float* b2      = (const float*)d_in[14];
    const float* fc_w    = (const float*)d_in[15];
    const float* fc_b    = (const float*)d_in[16];
    const float* bn_g    = (const float*)d_in[17];
    const float* bn_b    = (const float*)d_in[18];
    float* out = (float*)d_out;

    const int* src = eidx;
    const int* dst = eidx + EE;

    float *ph, *py;
    cudaGetSymbolAddress((void**)&ph, g_h);
    cudaGetSymbolAddress((void**)&py, g_y);

    hist_kernel<<<(EE + 255) / 256, 256>>>(dst);
    scan_kernel<<<1, 1024>>>();
    scatter_kernel<<<(EE + NN + 255) / 256, 256>>>(src, dst);

    const int gemm_grid = (NN + 127) / 128;
    const int warp_grid = (NN + 7) / 8;

    gemm_kernel<<<gemm_grid, 256>>>(x, W0, ph, NN, 64, a_src0, a_dst0);
    agg_kernel<<<warp_grid, 256>>>(ph, b0, py);

    gemm_kernel<<<gemm_grid, 256>>>(py, W1, ph, NN, 128, a_src1, a_dst1);
    agg_kernel<<<warp_grid, 256>>>(ph, b1, py);

    gemm_kernel<<<gemm_grid, 256>>>(py, W2, ph, NN, 128, a_src2, a_dst2);
    agg_kernel<<<warp_grid, 256>>>(ph, b2, py);

    gbound_kernel<<<(NN + 255) / 256, 256>>>(batch);
    pool_kernel<<<GG, 512>>>(py);
    head_kernel<<<GG, LAT>>>(fc_w, fc_b, bn_g, bn_b, out);
}

// round 9
// speedup vs baseline: 1.6206x; 1.0980x over previous
#include <cuda_runtime.h>
#include <cuda_bf16.h>
#include <stdint.h>
#include <math.h>

#define NN 50000
#define EE 800000
#define HID 128
#define GG 128
#define LAT 32
#define NEG 0.2f

// ---------------- scratch (static device memory; zero-initialized) ----------------
__device__ float g_h[NN * HID];
__device__ float g_y[NN * HID];
__device__ float g_as[NN * 4];
__device__ float g_ad[NN * 4];
__device__ int   g_deg[NN];          // invariant: zero before/after each launch
__device__ int   g_rowoff[NN + 1];
__device__ int   g_cur[NN];
__device__ int   g_csr[EE + NN];
__device__ int   g_goff[GG + 1];
__device__ float g_pool[GG * HID];

// ---------------- CSR build ----------------
__global__ void hist_kernel(const int* __restrict__ dst) {
    int i = blockIdx.x * blockDim.x + threadIdx.x;
    if (i < EE) atomicAdd(&g_deg[dst[i]], 1);
}

__global__ void scan_kernel() {
    __shared__ int sums[1024];
    const int T = 1024;
    int t = threadIdx.x;
    const int chunk = (NN + T - 1) / T;
    int start = t * chunk;
    int end = min(start + chunk, NN);
    int s = 0;
    for (int i = start; i < end; i++) s += g_deg[i] + 1;
    sums[t] = s;
    __syncthreads();
    for (int off = 1; off < T; off <<= 1) {
        int v = 0;
        if (t >= off) v = sums[t - off];
        __syncthreads();
        if (t >= off) sums[t] += v;
        __syncthreads();
    }
    int base = (t == 0) ? 0 : sums[t - 1];
    for (int i = start; i < end; i++) {
        g_rowoff[i] = base;
        g_cur[i] = base;
        base += g_deg[i] + 1;
        g_deg[i] = 0;
    }
    if (t == 0) g_rowoff[NN] = sums[T - 1];
}

__global__ void scatter_kernel(const int* __restrict__ src, const int* __restrict__ dst) {
    int i = blockIdx.x * blockDim.x + threadIdx.x;
    if (i < EE) {
        int d = dst[i];
        int pos = atomicAdd(&g_cur[d], 1);
        g_csr[pos] = src[i];
    } else if (i < EE + NN) {
        int n = i - EE;
        int pos = atomicAdd(&g_cur[n], 1);
        g_csr[pos] = n;
    }
}

__global__ void gbound_kernel(const int* __restrict__ batch) {
    int i = blockIdx.x * blockDim.x + threadIdx.x;
    if (i >= NN) return;
    int b = batch[i];
    int prev = (i == 0) ? -1 : batch[i - 1];
    for (int g = prev + 1; g <= b; g++) g_goff[g] = i;
    if (i == NN - 1) {
        for (int g = b + 1; g <= GG; g++) g_goff[g] = NN;
    }
}

// ---------------- HMMA bf16 split GEMM + fused alpha ----------------------------
// Out[n,128] = X[n,K] @ W[K,128] with X,W split into bf16 hi/lo:
//   D = Xh*Wh + Xl*Wh + Xh*Wl (fp32 acc)  -> rel err ~1e-5.
// Block: 128 rows x 128 cols, 8 warps. Warp: 32 rows x 64 cols = 2 m-tiles x 8
// n-tiles of mma.m16n8k16. Smem tiles stride 40 bf16 (80B) => conflict-free frags.
#define ASTR 40

#define MMA16816(d, a, b0v, b1v) \
    asm volatile("mma.sync.aligned.m16n8k16.row.col.f32.bf16.bf16.f32 " \
        "{%0,%1,%2,%3}, {%4,%5,%6,%7}, {%8,%9}, {%0,%1,%2,%3};" \
        : "+f"((d)[0]), "+f"((d)[1]), "+f"((d)[2]), "+f"((d)[3]) \
        : "r"((a)[0]), "r"((a)[1]), "r"((a)[2]), "r"((a)[3]), "r"(b0v), "r"(b1v))

__device__ __forceinline__ uint32_t pack_bf2(__nv_bfloat16 lo, __nv_bfloat16 hi) {
    return ((uint32_t)__bfloat16_as_ushort(hi) << 16) | __bfloat16_as_ushort(lo);
}

__global__ __launch_bounds__(256, 2) void gemm_kernel(
    const float* __restrict__ X, const float* __restrict__ W,
    float* __restrict__ Out, int nrows, int K,
    const float* __restrict__ a_src, const float* __restrict__ a_dst)
{
    __shared__ __align__(16) __nv_bfloat16 Ah_s[128 * ASTR];
    __shared__ __align__(16) __nv_bfloat16 Al_s[128 * ASTR];
    __shared__ __align__(16) __nv_bfloat16 Bh_s[128 * ASTR];
    __shared__ __align__(16) __nv_bfloat16 Bl_s[128 * ASTR];
    __shared__ float spart[128][4][2];
    __shared__ float sAs[128], sAd[128];

    int tid = threadIdx.x;
    int wid = tid >> 5, lane = tid & 31;
    int g = lane >> 2, tg = lane & 3;
    int rbase = (wid >> 1) * 32;
    int cbase = (wid & 1) * 64;
    int row0 = blockIdx.x * 128;

    if (tid < 128) { sAs[tid] = a_src[tid]; sAd[tid] = a_dst[tid]; }

    float acc[2][8][4];
#pragma unroll
    for (int mt = 0; mt < 2; mt++)
#pragma unroll
        for (int nt = 0; nt < 8; nt++)
#pragma unroll
            for (int q = 0; q < 4; q++) acc[mt][nt][q] = 0.f;

    int lrow = tid >> 1, lhalf = tid & 1;
    int grow = row0 + lrow;
    bool valid = grow < nrows;

    const int NCH = K >> 5;
    for (int ch = 0; ch < NCH; ch++) {
        // ---- stage A: X rows -> bf16 hi/lo, [row][k] ----
        {
            int k0 = lhalf * 16;
            const float4* xsrc = (const float4*)(X + (size_t)grow * K + ch * 32 + k0);
            uint32_t* dh = (uint32_t*)&Ah_s[lrow * ASTR + k0];
            uint32_t* dl = (uint32_t*)&Al_s[lrow * ASTR + k0];
#pragma unroll
            for (int j = 0; j < 4; j++) {
                float4 v = make_float4(0.f, 0.f, 0.f, 0.f);
                if (valid) v = __ldg(xsrc + j);
                __nv_bfloat16 h0 = __float2bfloat16(v.x), h1 = __float2bfloat16(v.y);
                __nv_bfloat16 h2 = __float2bfloat16(v.z), h3 = __float2bfloat16(v.w);
                __nv_bfloat16 l0 = __float2bfloat16(v.x - __bfloat162float(h0));
                __nv_bfloat16 l1 = __float2bfloat16(v.y - __bfloat162float(h1));
                __nv_bfloat16 l2 = __float2bfloat16(v.z - __bfloat162float(h2));
                __nv_bfloat16 l3 = __float2bfloat16(v.w - __bfloat162float(h3));
                dh[j * 2]     = pack_bf2(h0, h1);
                dh[j * 2 + 1] = pack_bf2(h2, h3);
                dl[j * 2]     = pack_bf2(l0, l1);
                dl[j * 2 + 1] = pack_bf2(l2, l3);
            }
        }
        // ---- stage B: W[k][n] -> transposed bf16 hi/lo, [n][k] ----
        {
            int n = lrow;
            int kk0 = ch * 32 + lhalf * 16;
            uint32_t* dh = (uint32_t*)&Bh_s[n * ASTR + lhalf * 16];
            uint32_t* dl = (uint32_t*)&Bl_s[n * ASTR + lhalf * 16];
#pragma unroll
            for (int p = 0; p < 8; p++) {
                float w0 = __ldg(W + (size_t)(kk0 + 2 * p) * 128 + n);
                float w1 = __ldg(W + (size_t)(kk0 + 2 * p + 1) * 128 + n);
                __nv_bfloat16 h0 = __float2bfloat16(w0), h1 = __float2bfloat16(w1);
                __nv_bfloat16 l0 = __float2bfloat16(w0 - __bfloat162float(h0));
                __nv_bfloat16 l1 = __float2bfloat16(w1 - __bfloat162float(h1));
                dh[p] = pack_bf2(h0, h1);
                dl[p] = pack_bf2(l0, l1);
            }
        }
        __syncthreads();

#pragma unroll
        for (int ks = 0; ks < 2; ks++) {
            int kb = ks * 16;
            uint32_t ah[2][4], al[2][4];
#pragma unroll
            for (int mt = 0; mt < 2; mt++) {
                int r = rbase + mt * 16 + g;
                const __nv_bfloat16* ap = &Ah_s[r * ASTR + kb + tg * 2];
                ah[mt][0] = *(const uint32_t*)ap;
                ah[mt][1] = *(const uint32_t*)(ap + 8 * ASTR);
                ah[mt][2] = *(const uint32_t*)(ap + 8);
                ah[mt][3] = *(const uint32_t*)(ap + 8 * ASTR + 8);
                const __nv_bfloat16* lp = &Al_s[r * ASTR + kb + tg * 2];
                al[mt][0] = *(const uint32_t*)lp;
                al[mt][1] = *(const uint32_t*)(lp + 8 * ASTR);
                al[mt][2] = *(const uint32_t*)(lp + 8);
                al[mt][3] = *(const uint32_t*)(lp + 8 * ASTR + 8);
            }
#pragma unroll
            for (int nt = 0; nt < 8; nt++) {
                int nb = cbase + nt * 8 + g;
                const __nv_bfloat16* bp = &Bh_s[nb * ASTR + kb + tg * 2];
                uint32_t bh0 = *(const uint32_t*)bp;
                uint32_t bh1 = *(const uint32_t*)(bp + 8);
                const __nv_bfloat16* qp = &Bl_s[nb * ASTR + kb + tg * 2];
                uint32_t bl0 = *(const uint32_t*)qp;
                uint32_t bl1 = *(const uint32_t*)(qp + 8);
#pragma unroll
                for (int mt = 0; mt < 2; mt++) {
                    MMA16816(acc[mt][nt], ah[mt], bh0, bh1);
                    MMA16816(acc[mt][nt], al[mt], bh0, bh1);
                    MMA16816(acc[mt][nt], ah[mt], bl0, bl1);
                }
            }
        }
        __syncthreads();
    }

    // ---- fused alpha partials (per-head; heads col-disjoint across warps) ----
    {
        float pA[2][2][2], pD[2][2][2];   // [mt][sub(row g / g+8)][head-half]
#pragma unroll
        for (int mt = 0; mt < 2; mt++)
#pragma unroll
            for (int sb = 0; sb < 2; sb++)
#pragma unroll
                for (int hh = 0; hh < 2; hh++) { pA[mt][sb][hh] = 0.f; pD[mt][sb][hh] = 0.f; }
#pragma unroll
        for (int mt = 0; mt < 2; mt++)
#pragma unroll
            for (int nt = 0; nt < 8; nt++) {
                int hh = nt >> 2;
                int c0 = cbase + nt * 8 + tg * 2;
                float a0 = sAs[c0], a1 = sAs[c0 + 1];
                float d0 = sAd[c0], d1 = sAd[c0 + 1];
                pA[mt][0][hh] += acc[mt][nt][0] * a0 + acc[mt][nt][1] * a1;
                pA[mt][1][hh] += acc[mt][nt][2] * a0 + acc[mt][nt][3] * a1;
                pD[mt][0][hh] += acc[mt][nt][0] * d0 + acc[mt][nt][1] * d1;
                pD[mt][1][hh] += acc[mt][nt][2] * d0 + acc[mt][nt][3] * d1;
            }
#pragma unroll
        for (int mt = 0; mt < 2; mt++)
#pragma unroll
            for (int sb = 0; sb < 2; sb++)
#pragma unroll
                for (int hh = 0; hh < 2; hh++) {
                    float vA = pA[mt][sb][hh], vD = pD[mt][sb][hh];
                    vA += __shfl_xor_sync(0xffffffffu, vA, 1);
                    vA += __shfl_xor_sync(0xffffffffu, vA, 2);
                    vD += __shfl_xor_sync(0xffffffffu, vD, 1);
                    vD += __shfl_xor_sync(0xffffffffu, vD, 2);
                    if (tg == 0) {
                        int row = rbase + mt * 16 + sb * 8 + g;
                        int head = (wid & 1) * 2 + hh;
                        spart[row][head][0] = vA;
                        spart[row][head][1] = vD;
                    }
                }
    }

    // ---- store Out ----
#pragma unroll
    for (int mt = 0; mt < 2; mt++) {
        int r1 = row0 + rbase + mt * 16 + g;
        int r2 = r1 + 8;
#pragma unroll
        for (int nt = 0; nt < 8; nt++) {
            int c = cbase + nt * 8 + tg * 2;
            if (r1 < nrows)
                *(float2*)&Out[(size_t)r1 * 128 + c] = make_float2(acc[mt][nt][0], acc[mt][nt][1]);
            if (r2 < nrows)
                *(float2*)&Out[(size_t)r2 * 128 + c] = make_float2(acc[mt][nt][2], acc[mt][nt][3]);
        }
    }

    __syncthreads();
    if (tid < 128) {
        int gr = row0 + tid;
        if (gr < nrows) {
            *(float4*)&g_as[gr * 4] = make_float4(spart[tid][0][0], spart[tid][1][0],
                                                  spart[tid][2][0], spart[tid][3][0]);
            *(float4*)&g_ad[gr * 4] = make_float4(spart[tid][0][1], spart[tid][1][1],
                                                  spart[tid][2][1], spart[tid][3][1]);
        }
    }
}

// ---------------- aggregation: one warp per dst node, two-pass softmax ----------
__global__ __launch_bounds__(256) void agg_kernel(
    const float* __restrict__ hbuf, const float* __restrict__ bias,
    float* __restrict__ outbuf)
{
    __shared__ int    s_src[8][32];
    __shared__ float4 s_p[8][32];

    int wi = threadIdx.x >> 5;
    int n = (blockIdx.x * blockDim.x + threadIdx.x) >> 5;
    if (n >= NN) return;
    int lane = threadIdx.x & 31;
    int head = lane >> 3;
    int col = head * 32 + (lane & 7) * 4;

    float4 adv = *(const float4*)&g_ad[n * 4];
    int beg = g_rowoff[n], end = g_rowoff[n + 1];

    float4 mx = make_float4(-1e30f, -1e30f, -1e30f, -1e30f);
    for (int p = beg + lane; p < end; p += 32) {
        int s = __ldg(&g_csr[p]);
        float4 a = __ldg((const float4*)&g_as[s * 4]);
        float e;
        e = a.x + adv.x; mx.x = fmaxf(mx.x, fmaxf(e, NEG * e));
        e = a.y + adv.y; mx.y = fmaxf(mx.y, fmaxf(e, NEG * e));
        e = a.z + adv.z; mx.z = fmaxf(mx.z, fmaxf(e, NEG * e));
        e = a.w + adv.w; mx.w = fmaxf(mx.w, fmaxf(e, NEG * e));
    }
#pragma unroll
    for (int off = 16; off; off >>= 1) {
        mx.x = fmaxf(mx.x, __shfl_xor_sync(0xffffffffu, mx.x, off));
        mx.y = fmaxf(mx.y, __shfl_xor_sync(0xffffffffu, mx.y, off));
        mx.z = fmaxf(mx.z, __shfl_xor_sync(0xffffffffu, mx.z, off));
        mx.w = fmaxf(mx.w, __shfl_xor_sync(0xffffffffu, mx.w, off));
    }

    float4 acc = make_float4(0.f, 0.f, 0.f, 0.f);
    float4 ss  = acc;

    for (int p0 = beg; p0 < end; p0 += 32) {
        int cnt = min(32, end - p0);
        float4 pv = make_float4(0.f, 0.f, 0.f, 0.f);
        int s = 0;
        if (lane < cnt) {
            s = __ldg(&g_csr[p0 + lane]);
            float4 a = __ldg((const float4*)&g_as[s * 4]);
            float e;
            e = a.x + adv.x; e = fmaxf(e, NEG * e); pv.x = __expf(e - mx.x);
            e = a.y + adv.y; e = fmaxf(e, NEG * e); pv.y = __expf(e - mx.y);
            e = a.z + adv.z; e = fmaxf(e, NEG * e); pv.z = __expf(e - mx.z);
            e = a.w + adv.w; e = fmaxf(e, NEG * e); pv.w = __expf(e - mx.w);
            ss.x += pv.x; ss.y += pv.y; ss.z += pv.z; ss.w += pv.w;
        }
        s_src[wi][lane] = s;
        s_p[wi][lane] = pv;
        __syncwarp();
        for (int j = 0; j < cnt; j++) {
            int sj = s_src[wi][j];
            float pj = ((const float*)&s_p[wi][j])[head];
            float4 hv = __ldg((const float4*)(hbuf + sj * 128 + col));
            acc.x = fmaf(pj, hv.x, acc.x);
            acc.y = fmaf(pj, hv.y, acc.y);
            acc.z = fmaf(pj, hv.z, acc.z);
            acc.w = fmaf(pj, hv.w, acc.w);
        }
        __syncwarp();
    }

#pragma unroll
    for (int off = 16; off; off >>= 1) {
        ss.x += __shfl_xor_sync(0xffffffffu, ss.x, off);
        ss.y += __shfl_xor_sync(0xffffffffu, ss.y, off);
        ss.z += __shfl_xor_sync(0xffffffffu, ss.z, off);
        ss.w += __shfl_xor_sync(0xffffffffu, ss.w, off);
    }
    float sh = (head == 0) ? ss.x : (head == 1) ? ss.y : (head == 2) ? ss.z : ss.w;
    float inv = 1.0f / (sh + 1e-16f);

    float4 b = *(const float4*)(bias + col);
    float4 o;
    o.x = acc.x * inv + b.x; o.x = fmaxf(o.x, NEG * o.x);
    o.y = acc.y * inv + b.y; o.y = fmaxf(o.y, NEG * o.y);
    o.z = acc.z * inv + b.z; o.z = fmaxf(o.z, NEG * o.z);
    o.w = acc.w * inv + b.w; o.w = fmaxf(o.w, NEG * o.w);
    *(float4*)(outbuf + n * 128 + col) = o;
}

// ---------------- pooling: segmented over sorted batch ----------------
__global__ __launch_bounds__(512) void pool_kernel(const float* __restrict__ y) {
    __shared__ float sh[3][128];
    int g = blockIdx.x;
    int s = g_goff[g], e = g_goff[g + 1];
    int c = threadIdx.x & 127;
    int r = threadIdx.x >> 7;
    float acc = 0.f;
    for (int i = s + r; i < e; i += 4) acc += y[i * 128 + c];
    if (r) sh[r - 1][c] = acc;
    __syncthreads();
    if (!r) g_pool[g * 128 + c] = ((acc + sh[0][c]) + (sh[1][c] + sh[2][c]));
}

// ---------------- head ----------------
__global__ void head_kernel(const float* __restrict__ fc_w, const float* __restrict__ fc_b,
                            const float* __restrict__ bn_g, const float* __restrict__ bn_b,
                            float* __restrict__ out)
{
    int g = blockIdx.x;
    int l = threadIdx.x;
    const float* pr = g_pool + g * HID;
    float s = 0.f;
#pragma unroll 8
    for (int k = 0; k < HID; k++) s = fmaf(pr[k], fc_w[k * LAT + l], s);
    s += fc_b[l];
    const float inv = 0.999995000037499688f;  // 1/sqrt(1 + 1e-5)
    out[g * LAT + l] = bn_g[l] * s * inv + bn_b[l];
}

// ---------------- launch ----------------
extern "C" void kernel_launch(void* const* d_in, const int* in_sizes, int n_in,
                              void* d_out, int out_size)
{
    const float* x       = (const float*)d_in[0];
    const int*   eidx    = (const int*)  d_in[1];
    const int*   batch   = (const int*)  d_in[2];
    const float* W0      = (const float*)d_in[3];
    const float* a_src0  = (const float*)d_in[4];
    const float* a_dst0  = (const float*)d_in[5];
    const float* b0      = (const float*)d_in[6];
    const float* W1      = (const float*)d_in[7];
    const float* a_src1  = (const float*)d_in[8];
    const float* a_dst1  = (const float*)d_in[9];
    const float* b1      = (const float*)d_in[10];
    const float* W2      = (const float*)d_in[11];
    const float* a_src2  = (const float*)d_in[12];
    const float* a_dst2  = (const float*)d_in[13];
    const float* b2      = (const float*)d_in[14];
    const float* fc_w    = (const float*)d_in[15];
    const float* fc_b    = (const float*)d_in[16];
    const float* bn_g    = (const float*)d_in[17];
    const float* bn_b    = (const float*)d_in[18];
    float* out = (float*)d_out;

    const int* src = eidx;
    const int* dst = eidx + EE;

    float *ph, *py;
    cudaGetSymbolAddress((void**)&ph, g_h);
    cudaGetSymbolAddress((void**)&py, g_y);

    hist_kernel<<<(EE + 255) / 256, 256>>>(dst);
    scan_kernel<<<1, 1024>>>();
    scatter_kernel<<<(EE + NN + 255) / 256, 256>>>(src, dst);

    const int gemm_grid = (NN + 127) / 128;
    const int warp_grid = (NN + 7) / 8;

    gemm_kernel<<<gemm_grid, 256>>>(x, W0, ph, NN, 64, a_src0, a_dst0);
    agg_kernel<<<warp_grid, 256>>>(ph, b0, py);

    gemm_kernel<<<gemm_grid, 256>>>(py, W1, ph, NN, HID, a_src1, a_dst1);
    agg_kernel<<<warp_grid, 256>>>(ph, b1, py);

    gemm_kernel<<<gemm_grid, 256>>>(py, W2, ph, NN, HID, a_src2, a_dst2);
    agg_kernel<<<warp_grid, 256>>>(ph, b2, py);

    gbound_kernel<<<(NN + 255) / 256, 256>>>(batch);
    pool_kernel<<<GG, 512>>>(py);
    head_kernel<<<GG, LAT>>>(fc_w, fc_b, bn_g, bn_b, out);
}